// round 7
// baseline (speedup 1.0000x reference)
#include <cuda_runtime.h>
#include <cuda_bf16.h>

// out[i] = sum_k targets[i,k] * temporal_bases[batch_indices[1], k] * scaling[k]
// B=8192, K=1024, T=16384. HBM-streaming GEMV (32 MB of targets, read once).
// Warp-per-row, double-buffered prefetch, atomic-ticket work stealing,
// grid = 2 CTAs/SM exactly for balanced residency.

static constexpr int K = 1024;
static constexpr int THREADS = 256;            // 8 warps
static constexpr int WARPS = THREADS / 32;
static constexpr int F4 = K / 4 / 32;          // 8 float4 per lane per row
static constexpr int NUM_SMS = 148;
static constexpr int GRID = NUM_SMS * 2;       // 296 CTAs, 2368 warps

__device__ int g_ticket;

__global__ void init_ticket_kernel(int start) {
    if (threadIdx.x == 0) g_ticket = start;
}

__device__ __forceinline__ int next_row(int lane) {
    int r = 0;
    if (lane == 0) r = atomicAdd(&g_ticket, 1);
    return __shfl_sync(0xffffffffu, r, 0);
}

__device__ __forceinline__ void load_row(const float* __restrict__ targets,
                                         int row, int lane, float4 (&buf)[F4]) {
    const float4* __restrict__ a4 = reinterpret_cast<const float4*>(targets + (size_t)row * K);
    #pragma unroll
    for (int j = 0; j < F4; j++)
        buf[j] = a4[lane + 32 * j];
}

__device__ __forceinline__ void reduce_store(const float4 (&a)[F4], const float4 (&c)[F4],
                                             int lane, float* __restrict__ out, int row) {
    float s = 0.0f;
    #pragma unroll
    for (int j = 0; j < F4; j++)
        s += a[j].x * c[j].x + a[j].y * c[j].y + a[j].z * c[j].z + a[j].w * c[j].w;
    #pragma unroll
    for (int off = 16; off > 0; off >>= 1)
        s += __shfl_xor_sync(0xffffffffu, s, off);
    if (lane == 0) out[row] = s;
}

__global__ __launch_bounds__(THREADS, 2)
void recompose_gemv_kernel(const float* __restrict__ targets,
                           const float* __restrict__ bases,
                           const float* __restrict__ scaling,
                           const int* __restrict__ batch_indices,
                           int B, int T,
                           float* __restrict__ out) {
    __shared__ float4 cs[K / 4];               // bases[t,:] * scaling (4 KB)

    int t = batch_indices[1];
    t = min(max(t, 0), T - 1);

    {   // stage combined vector once per CTA
        const float4 b = reinterpret_cast<const float4*>(bases + (size_t)t * K)[threadIdx.x];
        const float4 s = reinterpret_cast<const float4*>(scaling)[threadIdx.x];
        cs[threadIdx.x] = make_float4(b.x * s.x, b.y * s.y, b.z * s.z, b.w * s.w);
    }
    __syncthreads();

    const int warp = threadIdx.x >> 5;
    const int lane = threadIdx.x & 31;

    float4 c[F4];
    #pragma unroll
    for (int j = 0; j < F4; j++)
        c[j] = cs[lane + 32 * j];

    // First row is the static warp id; further rows come from the ticket
    // counter (initialized to total warp count by init kernel). Tickets are
    // monotonically increasing per warp, so once a ticket >= B is seen, no
    // later ticket can be < B: safe to stop.
    int rA = blockIdx.x * WARPS + warp;
    if (rA >= B) return;

    float4 A0[F4], A1[F4];
    load_row(targets, rA, lane, A0);

    int rB = next_row(lane);
    if (rB < B) load_row(targets, rB, lane, A1);

    while (true) {
        // draw next-next ticket early so ATOMG latency hides behind reduce
        int rC = (rB < B) ? next_row(lane) : B;

        reduce_store(A0, c, lane, out, rA);
        if (rB >= B) break;
        if (rC < B) load_row(targets, rC, lane, A0);

        int rD = (rC < B) ? next_row(lane) : B;

        reduce_store(A1, c, lane, out, rB);
        if (rC >= B) break;
        if (rD < B) load_row(targets, rD, lane, A1);

        rA = rC;
        rB = rD;
    }
}

extern "C" void kernel_launch(void* const* d_in, const int* in_sizes, int n_in,
                              void* d_out, int out_size) {
    // Resolve inputs by unique element counts, robust to metadata ordering.
    const float* targets = nullptr;   // B*K  = 8388608
    const float* bases   = nullptr;   // T*K  = 16777216
    const float* scaling = nullptr;   // K    = 1024
    const int*   indices = nullptr;   // B    = 8192
    long targets_n = 0, bases_n = 0;

    for (int j = 0; j < n_in; j++) {
        long n = in_sizes[j];
        if (n == K) {
            scaling = (const float*)d_in[j];
        } else if (n == 8192) {
            indices = (const int*)d_in[j];
        } else if (n == 8192L * K) {
            targets = (const float*)d_in[j];
            targets_n = n;
        } else {
            bases = (const float*)d_in[j];
            bases_n = n;
        }
    }
    if (!targets || !bases || !scaling || !indices) return;

    const int B = (int)(targets_n / K);   // 8192
    const int T = (int)(bases_n / K);     // 16384
    float* out = (float*)d_out;

    init_ticket_kernel<<<1, 32>>>(GRID * WARPS);
    recompose_gemv_kernel<<<GRID, THREADS>>>(targets, bases, scaling, indices, B, T, out);
}

// round 9
// speedup vs baseline: 1.1628x; 1.1628x over previous
#include <cuda_runtime.h>
#include <cuda_bf16.h>

// out[i] = sum_k targets[i,k] * temporal_bases[batch_indices[1], k] * scaling[k]
// B=8192, K=1024, T=16384. HBM-streaming GEMV (32 MB of targets, read once).
// Warp-per-row, 2 rows per pipeline stage, packed 64-bit shuffle reduce,
// grid = 2 CTAs/SM exactly (296) -> single wave, static interleaved work.

static constexpr int K = 1024;
static constexpr int THREADS = 256;            // 8 warps
static constexpr int WARPS = THREADS / 32;
static constexpr int F4 = K / 4 / 32;          // 8 float4 per lane per row
static constexpr int NUM_SMS = 148;
static constexpr int GRID = NUM_SMS * 2;       // 296 CTAs, 2368 warps, one wave

__device__ __forceinline__ void load_row(const float* __restrict__ targets,
                                         int row, int lane, float4 (&buf)[F4]) {
    const float4* __restrict__ a4 = reinterpret_cast<const float4*>(targets + (size_t)row * K);
    #pragma unroll
    for (int j = 0; j < F4; j++)
        buf[j] = a4[lane + 32 * j];
}

__device__ __forceinline__ float dot_row(const float4 (&a)[F4], const float4 (&c)[F4]) {
    float s = 0.0f;
    #pragma unroll
    for (int j = 0; j < F4; j++)
        s += a[j].x * c[j].x + a[j].y * c[j].y + a[j].z * c[j].z + a[j].w * c[j].w;
    return s;
}

// Reduce two per-lane partial sums across the warp with ONE 64-bit shuffle chain.
__device__ __forceinline__ void reduce2_store(float s0, float s1, int lane,
                                              float* __restrict__ out, int r0, int r1,
                                              bool w1) {
    double packed = __hiloint2double(__float_as_int(s1), __float_as_int(s0));
    #pragma unroll
    for (int off = 16; off > 0; off >>= 1) {
        double o = __shfl_xor_sync(0xffffffffu, packed, off);
        float a0 = __int_as_float(__double2loint(packed)) + __int_as_float(__double2loint(o));
        float a1 = __int_as_float(__double2hiint(packed)) + __int_as_float(__double2hiint(o));
        packed = __hiloint2double(__float_as_int(a1), __float_as_int(a0));
    }
    if (lane == 0) {
        out[r0] = __int_as_float(__double2loint(packed));
        if (w1) out[r1] = __int_as_float(__double2hiint(packed));
    }
}

__global__ __launch_bounds__(THREADS, 2)
void recompose_gemv_kernel(const float* __restrict__ targets,
                           const float* __restrict__ bases,
                           const float* __restrict__ scaling,
                           const int* __restrict__ batch_indices,
                           int B, int T,
                           float* __restrict__ out) {
    __shared__ float4 cs[K / 4];               // bases[t,:] * scaling (4 KB)

    int t = batch_indices[1];
    t = min(max(t, 0), T - 1);

    {   // stage combined vector once per CTA
        const float4 b = reinterpret_cast<const float4*>(bases + (size_t)t * K)[threadIdx.x];
        const float4 s = reinterpret_cast<const float4*>(scaling)[threadIdx.x];
        cs[threadIdx.x] = make_float4(b.x * s.x, b.y * s.y, b.z * s.z, b.w * s.w);
    }
    __syncthreads();

    const int warp = threadIdx.x >> 5;
    const int lane = threadIdx.x & 31;
    const int stride = GRID * WARPS;           // 2368

    float4 c[F4];
    #pragma unroll
    for (int j = 0; j < F4; j++)
        c[j] = cs[lane + 32 * j];

    int r0 = blockIdx.x * WARPS + warp;
    if (r0 >= B) return;
    int r1 = r0 + stride;

    float4 A0[F4], A1[F4];
    load_row(targets, r0, lane, A0);
    if (r1 < B) load_row(targets, r1, lane, A1);

    while (true) {
        // dots first (frees buffers), then prefetch next pair, then reduce:
        // the packed shuffle chain + stores overlap the in-flight loads.
        float s0 = dot_row(A0, c);
        float s1 = (r1 < B) ? dot_row(A1, c) : 0.0f;

        int n0 = r1 + stride;            // next pair
        int n1 = n0 + stride;
        bool more = (r1 < B) && (n0 < B);
        if (more) {
            load_row(targets, n0, lane, A0);
            if (n1 < B) load_row(targets, n1, lane, A1);
        }

        reduce2_store(s0, s1, lane, out, r0, r1, r1 < B);

        if (!more) break;
        r0 = n0;
        r1 = n1;
    }
}

extern "C" void kernel_launch(void* const* d_in, const int* in_sizes, int n_in,
                              void* d_out, int out_size) {
    // Resolve inputs by unique element counts, robust to metadata ordering.
    const float* targets = nullptr;   // B*K  = 8388608
    const float* bases   = nullptr;   // T*K  = 16777216
    const float* scaling = nullptr;   // K    = 1024
    const int*   indices = nullptr;   // B    = 8192
    long targets_n = 0, bases_n = 0;

    for (int j = 0; j < n_in; j++) {
        long n = in_sizes[j];
        if (n == K) {
            scaling = (const float*)d_in[j];
        } else if (n == 8192) {
            indices = (const int*)d_in[j];
        } else if (n == 8192L * K) {
            targets = (const float*)d_in[j];
            targets_n = n;
        } else {
            bases = (const float*)d_in[j];
            bases_n = n;
        }
    }
    if (!targets || !bases || !scaling || !indices) return;

    const int B = (int)(targets_n / K);   // 8192
    const int T = (int)(bases_n / K);     // 16384
    float* out = (float*)d_out;

    recompose_gemv_kernel<<<GRID, THREADS>>>(targets, bases, scaling, indices, B, T, out);
}

// round 11
// speedup vs baseline: 1.3793x; 1.1862x over previous
#include <cuda_runtime.h>
#include <cstdint>

// out[i] = sum_k targets[i,k] * temporal_bases[batch_indices[1], k] * scaling[k]
// B=8192, K=1024, T=16384. HBM-streaming GEMV (32 MB of targets, read once).
// cp.async.bulk (TMA 1D) -> smem ring (3 stages x 32 KB) -> warp-per-row dot.

static constexpr int K = 1024;
static constexpr int THREADS = 256;                 // 8 warps
static constexpr int WARPS = 8;
static constexpr int F4 = K / 4 / 32;               // 8 float4 per lane per row
static constexpr int CHUNK_ROWS = 8;                // one row per warp per chunk
static constexpr unsigned CHUNK_BYTES = CHUNK_ROWS * K * 4;  // 32768
static constexpr int STAGES = 3;
static constexpr int NUM_SMS = 148;
static constexpr int GRID = NUM_SMS * 2;            // 296 CTAs, single wave

static constexpr int OFF_FULL  = 0;                  // 3 x u64
static constexpr int OFF_EMPTY = 64;                 // 3 x u64
static constexpr int OFF_C     = 128;                // 4 KB combined vector
static constexpr int OFF_RING  = 8192;               // 3 x 32 KB
static constexpr int SMEM_SIZE = OFF_RING + STAGES * (int)CHUNK_BYTES;  // 106496

__device__ __forceinline__ uint32_t smem_u32(const void* p) {
    return (uint32_t)__cvta_generic_to_shared(p);
}
__device__ __forceinline__ void mbar_init(uint32_t a, uint32_t cnt) {
    asm volatile("mbarrier.init.shared.b64 [%0], %1;" :: "r"(a), "r"(cnt) : "memory");
}
__device__ __forceinline__ void mbar_expect_tx(uint32_t a, uint32_t bytes) {
    asm volatile("mbarrier.arrive.expect_tx.shared.b64 _, [%0], %1;"
                 :: "r"(a), "r"(bytes) : "memory");
}
__device__ __forceinline__ void mbar_arrive(uint32_t a) {
    asm volatile("mbarrier.arrive.shared::cta.b64 _, [%0];"
                 :: "r"(a) : "memory");
}
__device__ __forceinline__ void mbar_wait(uint32_t a, uint32_t parity) {
    asm volatile(
        "{\n\t"
        ".reg .pred P;\n\t"
        "WL_%=:\n\t"
        "mbarrier.try_wait.parity.acquire.cta.shared::cta.b64 P, [%0], %1, 0x989680;\n\t"
        "@P bra WD_%=;\n\t"
        "bra WL_%=;\n\t"
        "WD_%=:\n\t"
        "}"
        :: "r"(a), "r"(parity) : "memory");
}
__device__ __forceinline__ void bulk_g2s(uint32_t dst, const void* src,
                                         uint32_t bytes, uint32_t mbar) {
    asm volatile(
        "cp.async.bulk.shared::cta.global.mbarrier::complete_tx::bytes [%0], [%1], %2, [%3];"
        :: "r"(dst), "l"(src), "r"(bytes), "r"(mbar) : "memory");
}

__global__ __launch_bounds__(THREADS, 2)
void recompose_tma_kernel(const float* __restrict__ targets,
                          const float* __restrict__ bases,
                          const float* __restrict__ scaling,
                          const int* __restrict__ batch_indices,
                          int B, int T,
                          float* __restrict__ out) {
    extern __shared__ char smem[];
    const uint32_t base = smem_u32(smem);
    const uint32_t full0  = base + OFF_FULL;
    const uint32_t empty0 = base + OFF_EMPTY;
    float4* cs = reinterpret_cast<float4*>(smem + OFF_C);

    const int tid  = threadIdx.x;
    const int warp = tid >> 5;
    const int lane = tid & 31;

    if (tid == 0) {
        #pragma unroll
        for (int s = 0; s < STAGES; s++) {
            mbar_init(full0  + 8u * s, 1);       // completes via tx-count
            mbar_init(empty0 + 8u * s, WARPS);   // one arrive per warp (lane 0)
        }
    }

    int t = batch_indices[1];
    t = min(max(t, 0), T - 1);
    {
        const float4 b = reinterpret_cast<const float4*>(bases + (size_t)t * K)[tid];
        const float4 s = reinterpret_cast<const float4*>(scaling)[tid];
        cs[tid] = make_float4(b.x * s.x, b.y * s.y, b.z * s.z, b.w * s.w);
    }
    __syncthreads();   // barriers initialized + cs visible before any TMA/consume

    const int n_chunks = B / CHUNK_ROWS;                   // 1024
    const int n_local  = (n_chunks - blockIdx.x + gridDim.x - 1) / gridDim.x;
    if (n_local <= 0) return;

    // ---- prologue: fill the ring ----
    if (tid == 0) {
        const int npro = n_local < STAGES ? n_local : STAGES;
        for (int j = 0; j < npro; j++) {
            const int g = blockIdx.x + j * gridDim.x;
            const uint32_t fb = full0 + 8u * j;
            mbar_expect_tx(fb, CHUNK_BYTES);
            bulk_g2s(base + OFF_RING + j * CHUNK_BYTES,
                     targets + (size_t)g * CHUNK_ROWS * K, CHUNK_BYTES, fb);
        }
    }

    float4 c[F4];
    #pragma unroll
    for (int j = 0; j < F4; j++)
        c[j] = cs[lane + 32 * j];

    for (int j = 0; j < n_local; j++) {
        const int s = j % STAGES;
        const uint32_t par = (uint32_t)(j / STAGES) & 1u;
        const int g = blockIdx.x + j * gridDim.x;
        const int row = g * CHUNK_ROWS + warp;

        mbar_wait(full0 + 8u * s, par);

        const float4* __restrict__ a4 = reinterpret_cast<const float4*>(
            smem + OFF_RING + s * CHUNK_BYTES + warp * (K * 4));

        float sum = 0.0f;
        #pragma unroll
        for (int q = 0; q < F4; q++) {
            const float4 a = a4[lane + 32 * q];
            sum += a.x * c[q].x + a.y * c[q].y + a.z * c[q].z + a.w * c[q].w;
        }
        #pragma unroll
        for (int off = 16; off > 0; off >>= 1)
            sum += __shfl_xor_sync(0xffffffffu, sum, off);

        if (lane == 0) {
            out[row] = sum;
            mbar_arrive(empty0 + 8u * s);
        }

        // refill this stage for chunk j + STAGES
        if (tid == 0 && j + STAGES < n_local) {
            mbar_wait(empty0 + 8u * s, par);     // all 8 warps released stage s
            const int gn = blockIdx.x + (j + STAGES) * gridDim.x;
            const uint32_t fb = full0 + 8u * s;
            mbar_expect_tx(fb, CHUNK_BYTES);
            bulk_g2s(base + OFF_RING + s * CHUNK_BYTES,
                     targets + (size_t)gn * CHUNK_ROWS * K, CHUNK_BYTES, fb);
        }
    }
}

extern "C" void kernel_launch(void* const* d_in, const int* in_sizes, int n_in,
                              void* d_out, int out_size) {
    const float* targets = nullptr;   // B*K
    const float* bases   = nullptr;   // T*K
    const float* scaling = nullptr;   // K
    const int*   indices = nullptr;   // B
    long targets_n = 0, bases_n = 0;

    for (int j = 0; j < n_in; j++) {
        long n = in_sizes[j];
        if (n == K) {
            scaling = (const float*)d_in[j];
        } else if (n == 8192) {
            indices = (const int*)d_in[j];
        } else if (n == 8192L * K) {
            targets = (const float*)d_in[j];
            targets_n = n;
        } else {
            bases = (const float*)d_in[j];
            bases_n = n;
        }
    }
    if (!targets || !bases || !scaling || !indices) return;

    const int B = (int)(targets_n / K);   // 8192
    const int T = (int)(bases_n / K);     // 16384
    float* out = (float*)d_out;

    static bool attr_set = false;
    if (!attr_set) {
        cudaFuncSetAttribute(recompose_tma_kernel,
                             cudaFuncAttributeMaxDynamicSharedMemorySize, SMEM_SIZE);
        attr_set = true;
    }
    recompose_tma_kernel<<<GRID, THREADS, SMEM_SIZE>>>(targets, bases, scaling,
                                                       indices, B, T, out);
}